// round 14
// baseline (speedup 1.0000x reference)
#include <cuda_runtime.h>
#include <cuda_bf16.h>
#include <math.h>
#include <stdint.h>

// Shapes: B=256, hn=12, N1=12, dim=inner=1024
#define MROWS   36864
#define BHCOUNT 3072
#define DIM     1024
#define SLAB    37748736ULL          // MROWS * DIM

// fp32 slabs: 0 emb_r, 1 emb_t, 2 norm_r, 3 norm_t, 4 ln_r(->ao_r), 5 ln_t(->ao_t),
//             6 q_r, 7 q_t, 8 k_r, 9 k_t, 10 v_r, 11 v_t   (pairs adjacent!)
__device__ float g_f32[12 * SLAB];
__device__ float g_w[5ULL * 1024 * 1024];   // tf32-rounded weights
__device__ float g_stats[48];   // [0:12) sum_r, [12:24) sq_r, [24:36) sum_t, [36:48) sq_t
__device__ float g_coef[48];

// ---------------------------------------------------------------------------
__global__ void zero_stats_kernel() {
    if (threadIdx.x < 48) g_stats[threadIdx.x] = 0.0f;
}

// ---------------------------------------------------------------------------
// helpers
// ---------------------------------------------------------------------------
__device__ __forceinline__ uint32_t swz128(uint32_t o) { return o ^ ((o >> 3) & 0x70); }

__device__ __forceinline__ void cp_async16(uint32_t saddr, const void* gaddr) {
    asm volatile("cp.async.cg.shared.global [%0], [%1], 16;\n" :: "r"(saddr), "l"(gaddr));
}
__device__ __forceinline__ void cp_commit() { asm volatile("cp.async.commit_group;\n"); }

__device__ __forceinline__ float to_tf32(float x) {
    float r;
    asm("cvt.rna.tf32.f32 %0, %1;" : "=f"(r) : "f"(x));
    return r;
}
__device__ __forceinline__ uint32_t round_u32(uint32_t x) {
    return __float_as_uint(to_tf32(__uint_as_float(x)));
}

__device__ __forceinline__ void ldsm4(uint32_t& r0, uint32_t& r1, uint32_t& r2,
                                      uint32_t& r3, uint32_t addr) {
    asm volatile("ldmatrix.sync.aligned.m8n8.x4.shared.b16 {%0,%1,%2,%3}, [%4];\n"
                 : "=r"(r0), "=r"(r1), "=r"(r2), "=r"(r3) : "r"(addr));
}

__device__ __forceinline__ void mma_tf32(float* d, const uint32_t* a, const uint32_t* b) {
    asm volatile(
        "mma.sync.aligned.m16n8k8.row.col.f32.tf32.tf32.f32 "
        "{%0,%1,%2,%3},{%4,%5,%6,%7},{%8,%9},{%0,%1,%2,%3};\n"
        : "+f"(d[0]), "+f"(d[1]), "+f"(d[2]), "+f"(d[3])
        : "r"(a[0]), "r"(a[1]), "r"(a[2]), "r"(a[3]), "r"(b[0]), "r"(b[1]));
}

__device__ __forceinline__ uint32_t smem_u32(const void* p) {
    uint32_t a;
    asm("{ .reg .u64 t; cvta.to.shared.u64 t, %1; cvt.u32.u64 %0, t; }" : "=r"(a) : "l"(p));
    return a;
}

// ---------------------------------------------------------------------------
// round an fp32 array to tf32 (RN). grid = n/1024, block 256, float4/thread.
// ---------------------------------------------------------------------------
__global__ void cvt_tf32_kernel(const float* __restrict__ in, float* __restrict__ out)
{
    size_t i = ((size_t)blockIdx.x * 256 + threadIdx.x) * 4;
    float4 v = *(const float4*)(in + i);
    v.x = to_tf32(v.x); v.y = to_tf32(v.y);
    v.z = to_tf32(v.z); v.w = to_tf32(v.w);
    *(float4*)(out + i) = v;
}

// ---------------------------------------------------------------------------
// tf32 GEMM: C[M,1024] = A @ W^T + bias.
// CTA tile 256x128 (MxN), 8 warps (4x2), warp tile 64x64.
// k-tile 32 floats, 3-stage cp.async (48KB/stage), prefetch-2, 1 CTA/SM.
// ROUND_A: RN-round A fragments in registers (A is raw fp32).
// DO_STATS: per-channel (row%12) sum / sumsq of C into statsPtr.
// ---------------------------------------------------------------------------
#define TFSTAGE 49152              // 32KB A + 16KB B
#define TF_SMEM (3 * TFSTAGE)

template<bool ROUND_A, bool DO_STATS>
__global__ __launch_bounds__(256, 1) void tgemm_kernel(
    const float* __restrict__ A, const float* __restrict__ W,
    const float* __restrict__ bias, float* __restrict__ C,
    float* __restrict__ statsPtr)
{
    extern __shared__ char smem[];
    __shared__ float s_sum[256], s_sq[256];
    const uint32_t tiles = smem_u32(smem);
    const int tid = threadIdx.x, lane = tid & 31, warp = tid >> 5;
    const int bm = blockIdx.y, bn = blockIdx.x;
    const int m_off = (warp & 3) * 64, n_off = (warp >> 2) * 64;
    const int r0 = tid >> 3;     // 0..31
    const int ch = tid & 7;      // 16B chunk within 128B row

    if (DO_STATS) { s_sum[tid] = 0.0f; s_sq[tid] = 0.0f; }

    float acc[4][8][4];
#pragma unroll
    for (int i = 0; i < 4; i++)
#pragma unroll
        for (int j = 0; j < 8; j++)
#pragma unroll
            for (int r = 0; r < 4; r++) acc[i][j][r] = 0.0f;

    auto load_tile = [&](int stage, int kt) {
        const float* Ag = A + (size_t)(bm * 256 + r0) * DIM + kt * 32 + ch * 4;
        const float* Wg = W + (size_t)(bn * 128 + r0) * DIM + kt * 32 + ch * 4;
        uint32_t sa = tiles + stage * TFSTAGE;
        uint32_t sb = sa + 32768;
#pragma unroll
        for (int j = 0; j < 8; j++) {
            uint32_t so = swz128((uint32_t)(r0 + 32 * j) * 128 + ch * 16);
            cp_async16(sa + so, Ag + (size_t)(32 * j) * DIM);
        }
#pragma unroll
        for (int j = 0; j < 4; j++) {
            uint32_t so = swz128((uint32_t)(r0 + 32 * j) * 128 + ch * 16);
            cp_async16(sb + so, Wg + (size_t)(32 * j) * DIM);
        }
        cp_commit();
    };

    load_tile(0, 0); load_tile(1, 1);

#pragma unroll 1
    for (int kt = 0; kt < 32; kt++) {
        if (kt < 31) asm volatile("cp.async.wait_group 1;\n" ::: "memory");
        else         asm volatile("cp.async.wait_group 0;\n" ::: "memory");
        __syncthreads();

        if (kt + 2 < 32) load_tile((kt + 2) % 3, kt + 2);

        uint32_t sa = tiles + (kt % 3) * TFSTAGE;
        uint32_t sb = sa + 32768;
#pragma unroll
        for (int kk = 0; kk < 4; kk++) {           // 4 k8 steps per 32-float tile
            uint32_t afr[4][4], bfr[8][2];
#pragma unroll
            for (int i = 0; i < 4; i++) {
                int row = m_off + i * 16 + (lane & 15);
                uint32_t addr = sa + swz128((uint32_t)row * 128 + (2 * kk + (lane >> 4)) * 16);
                ldsm4(afr[i][0], afr[i][1], afr[i][2], afr[i][3], addr);
                if (ROUND_A) {
#pragma unroll
                    for (int r = 0; r < 4; r++) afr[i][r] = round_u32(afr[i][r]);
                }
            }
#pragma unroll
            for (int jj = 0; jj < 4; jj++) {
                int row = n_off + jj * 16 + (lane & 7) + ((lane >> 4) << 3);
                uint32_t addr = sb + swz128((uint32_t)row * 128 + (2 * kk + ((lane >> 3) & 1)) * 16);
                ldsm4(bfr[2 * jj][0], bfr[2 * jj][1], bfr[2 * jj + 1][0], bfr[2 * jj + 1][1], addr);
            }
#pragma unroll
            for (int i = 0; i < 4; i++)
#pragma unroll
                for (int j = 0; j < 8; j++) mma_tf32(acc[i][j], afr[i], bfr[j]);
        }
    }

    // epilogue
    const int gr = lane >> 2, gc = (lane & 3) * 2;
    float rsum[8], rsq[8];
#pragma unroll
    for (int i = 0; i < 8; i++) { rsum[i] = 0.0f; rsq[i] = 0.0f; }
#pragma unroll
    for (int i = 0; i < 4; i++) {
        size_t rowg = (size_t)(bm * 256 + m_off + i * 16 + gr);
#pragma unroll
        for (int j = 0; j < 8; j++) {
            int col = bn * 128 + n_off + j * 8 + gc;
            float b0 = __ldg(bias + col), b1 = __ldg(bias + col + 1);
            float2 o0 = make_float2(acc[i][j][0] + b0, acc[i][j][1] + b1);
            float2 o1 = make_float2(acc[i][j][2] + b0, acc[i][j][3] + b1);
            *(float2*)(C + rowg * DIM + col)       = o0;
            *(float2*)(C + (rowg + 8) * DIM + col) = o1;
            if (DO_STATS) {
                rsum[2 * i]     += o0.x + o0.y;
                rsq[2 * i]      += o0.x * o0.x + o0.y * o0.y;
                rsum[2 * i + 1] += o1.x + o1.y;
                rsq[2 * i + 1]  += o1.x * o1.x + o1.y * o1.y;
            }
        }
    }

    if (DO_STATS) {
#pragma unroll
        for (int i = 0; i < 4; i++) {
            int lr = m_off + i * 16 + gr;
            atomicAdd(&s_sum[lr],     rsum[2 * i]);
            atomicAdd(&s_sq[lr],      rsq[2 * i]);
            atomicAdd(&s_sum[lr + 8], rsum[2 * i + 1]);
            atomicAdd(&s_sq[lr + 8],  rsq[2 * i + 1]);
        }
        __syncthreads();
        int c = (bm * 256 + tid) % 12;
        atomicAdd(&statsPtr[c],      s_sum[tid]);
        atomicAdd(&statsPtr[12 + c], s_sq[tid]);
    }
}

// ---------------------------------------------------------------------------
// BN finalize: stats -> per-channel affine coefficients (both streams)
// ---------------------------------------------------------------------------
__global__ void bn_finalize_kernel(const float* __restrict__ bn_w,
                                   const float* __restrict__ bn_b)
{
    int c = threadIdx.x;
    if (c >= 12) return;
    const float inv_cnt = 1.0f / 3145728.0f;
    {
        float mean = g_stats[c] * inv_cnt;
        float var  = g_stats[12 + c] * inv_cnt - mean * mean;
        float A = bn_w[c] * rsqrtf(var + 1e-5f);
        g_coef[c] = A;  g_coef[12 + c] = bn_b[c] - mean * A;
    }
    {
        float mean = g_stats[24 + c] * inv_cnt;
        float var  = g_stats[36 + c] * inv_cnt - mean * mean;
        float A = bn_w[c] * rsqrtf(var + 1e-5f);
        g_coef[24 + c] = A;  g_coef[36 + c] = bn_b[c] - mean * A;
    }
}

// ---------------------------------------------------------------------------
// BN apply + pos add, tf32-rounded fp32 output. BOTH streams in one launch.
// ---------------------------------------------------------------------------
__global__ void bn_apply_kernel(const float* __restrict__ emb,   // slab 0 (r|t)
                                const float* __restrict__ pos,
                                float* __restrict__ normout)     // slab 2 (r|t)
{
    size_t row = blockIdx.x;             // 0 .. 2*MROWS-1
    int t = threadIdx.x;
    int stream = (int)(row >= MROWS);
    size_t lrow = row - (size_t)stream * MROWS;
    int coef_off = stream * 24;
    int c = (int)(lrow % 12);
    size_t b = lrow / 144;
    float A  = g_coef[coef_off + c];
    float Bc = g_coef[coef_off + 12 + c];
    float4 v = ((const float4*)(emb + row * DIM))[t];
    float4 p = ((const float4*)(pos + (b * 12 + (size_t)c) * DIM))[t];
    float4 o;
    o.x = to_tf32(v.x * A + Bc + p.x);
    o.y = to_tf32(v.y * A + Bc + p.y);
    o.z = to_tf32(v.z * A + Bc + p.z);
    o.w = to_tf32(v.w * A + Bc + p.w);
    ((float4*)(normout + row * DIM))[t] = o;
}

// ---------------------------------------------------------------------------
// LayerNorm -> tf32-rounded fp32 output. grid = MROWS, block 256.
// ---------------------------------------------------------------------------
__global__ void ln_kernel(const float* __restrict__ src, float* __restrict__ dst,
                          const float* __restrict__ w, const float* __restrict__ b)
{
    const size_t row = blockIdx.x;
    const int tid = threadIdx.x, lane = tid & 31, wrp = tid >> 5;
    __shared__ float ss[8], sq[8], mv[2];
    float4 v = ((const float4*)(src + row * DIM))[tid];
    float s = v.x + v.y + v.z + v.w;
    float q = v.x * v.x + v.y * v.y + v.z * v.z + v.w * v.w;
#pragma unroll
    for (int o = 16; o; o >>= 1) {
        s += __shfl_xor_sync(0xffffffffu, s, o);
        q += __shfl_xor_sync(0xffffffffu, q, o);
    }
    if (lane == 0) { ss[wrp] = s; sq[wrp] = q; }
    __syncthreads();
    if (tid == 0) {
        float S = 0.0f, Q = 0.0f;
#pragma unroll
        for (int i = 0; i < 8; i++) { S += ss[i]; Q += sq[i]; }
        float mean = S * (1.0f / 1024.0f);
        float var  = Q * (1.0f / 1024.0f) - mean * mean;
        mv[0] = mean;  mv[1] = rsqrtf(var + 1e-5f);
    }
    __syncthreads();
    float mean = mv[0], inv = mv[1];
    float4 wv = ((const float4*)w)[tid];
    float4 bv = ((const float4*)b)[tid];
    float4 o;
    o.x = to_tf32((v.x - mean) * inv * wv.x + bv.x);
    o.y = to_tf32((v.y - mean) * inv * wv.y + bv.y);
    o.z = to_tf32((v.z - mean) * inv * wv.z + bv.z);
    o.w = to_tf32((v.w - mean) * inv * wv.w + bv.w);
    ((float4*)(dst + row * DIM))[tid] = o;
}

// ---------------------------------------------------------------------------
// fused attention: logits(12x24) -> softmax -> attn @ V; tf32-rounded output
// ---------------------------------------------------------------------------
__global__ void attn_kernel(const float* __restrict__ q_r, const float* __restrict__ q_t,
                            const float* __restrict__ k_r, const float* __restrict__ k_t,
                            const float* __restrict__ v_r, const float* __restrict__ v_t,
                            float* __restrict__ ao_r, float* __restrict__ ao_t)
{
    const int bh = blockIdx.x;
    const bool tir = (blockIdx.y != 0);
    const size_t base = (size_t)bh * 12 * DIM;
    const float* Q = (tir ? q_t : q_r) + base;
    float* AO = (tir ? ao_t : ao_r) + base;
    const float* Kr = k_r + base;
    const float* Kt = k_t + base;
    const float* Vr = v_r + base;
    const float* Vt = v_t + base;

    __shared__ float att[12][24];
    const int tid = threadIdx.x, lane = tid & 31, wrp = tid >> 5;

    for (int dot = wrp; dot < 288; dot += 8) {
        int n1 = dot / 24, s = dot % 24;
        const float4* qp = (const float4*)(Q + (size_t)n1 * DIM);
        const float4* kp = (const float4*)((s < 12) ? (Kr + (size_t)s * DIM)
                                                    : (Kt + (size_t)(s - 12) * DIM));
        float acc = 0.0f;
        for (int d4 = lane; d4 < 256; d4 += 32) {
            float4 a = qp[d4]; float4 bb = kp[d4];
            acc += a.x * bb.x + a.y * bb.y + a.z * bb.z + a.w * bb.w;
        }
#pragma unroll
        for (int o = 16; o; o >>= 1) acc += __shfl_xor_sync(0xffffffffu, acc, o);
        if (lane == 0) att[n1][s] = acc;
    }
    __syncthreads();

    if (tid < 12) {
        const float scale = 0.03125f;
        float e[24], m = -1e30f;
#pragma unroll
        for (int s = 0; s < 24; s++) { float l = att[tid][s] * scale; e[s] = l; m = fmaxf(m, l); }
        float sum = 0.0f;
#pragma unroll
        for (int s = 0; s < 24; s++) { float x = expf(e[s] - m); e[s] = x; sum += x; }
        float inv = 1.0f / sum;
#pragma unroll
        for (int s = 0; s < 24; s++) att[tid][s] = e[s] * inv;
    }
    __syncthreads();

    for (int d = tid; d < DIM; d += 256) {
        float vc[24];
#pragma unroll
        for (int s = 0; s < 12; s++) vc[s]      = Vr[(size_t)s * DIM + d];
#pragma unroll
        for (int s = 0; s < 12; s++) vc[12 + s] = Vt[(size_t)s * DIM + d];
#pragma unroll
        for (int n1 = 0; n1 < 12; n1++) {
            float o = 0.0f;
#pragma unroll
            for (int s = 0; s < 24; s++) o += att[n1][s] * vc[s];
            AO[(size_t)n1 * DIM + d] = to_tf32(o);
        }
    }
}

// ---------------------------------------------------------------------------
extern "C" void kernel_launch(void* const* d_in, const int* in_sizes, int n_in,
                              void* d_out, int out_size)
{
    const float* attn_rgb = (const float*)d_in[0];
    const float* attn_tir = (const float*)d_in[1];
    const float* pos_emb  = (const float*)d_in[2];
    const float* embed_w  = (const float*)d_in[3];
    const float* embed_b  = (const float*)d_in[4];
    const float* bn_w     = (const float*)d_in[5];
    const float* bn_b     = (const float*)d_in[6];
    const float* ln_w     = (const float*)d_in[7];
    const float* ln_b     = (const float*)d_in[8];
    const float* v_w      = (const float*)d_in[9];
    const float* v_b      = (const float*)d_in[10];
    const float* q_w      = (const float*)d_in[11];
    const float* q_b      = (const float*)d_in[12];
    const float* k_w      = (const float*)d_in[13];
    const float* k_b      = (const float*)d_in[14];
    const float* out_w    = (const float*)d_in[15];
    const float* out_b    = (const float*)d_in[16];
    float* out = (float*)d_out;

    float* f32 = nullptr;   cudaGetSymbolAddress((void**)&f32, g_f32);
    float* wbuf = nullptr;  cudaGetSymbolAddress((void**)&wbuf, g_w);
    float* stats = nullptr; cudaGetSymbolAddress((void**)&stats, g_stats);

    float* emb   = f32 + 0 * SLAB;    // [0,1]: emb_r | emb_t
    float* norm  = f32 + 2 * SLAB;    // [2,3]: norm_r | norm_t
    float* lns   = f32 + 4 * SLAB;    // [4,5]: ln_r | ln_t  (reused as ao after V)
    float* qbuf  = f32 + 6 * SLAB;    // [6,7]
    float* kbuf  = f32 + 8 * SLAB;    // [8,9]
    float* vbuf  = f32 + 10 * SLAB;   // [10,11]

    const size_t WN = 1024ULL * 1024;
    float* w_embed = wbuf + 0 * WN;
    float* w_v     = wbuf + 1 * WN;
    float* w_q     = wbuf + 2 * WN;
    float* w_k     = wbuf + 3 * WN;
    float* w_out   = wbuf + 4 * WN;

    cudaFuncSetAttribute(tgemm_kernel<false, false>,
                         cudaFuncAttributeMaxDynamicSharedMemorySize, TF_SMEM);
    cudaFuncSetAttribute(tgemm_kernel<true, true>,
                         cudaFuncAttributeMaxDynamicSharedMemorySize, TF_SMEM);

    const dim3 grid1(8, 144);    // single-stream GEMM (M = 36864, m-tile 256)
    const dim3 grid2(8, 288);    // merged-pair GEMM  (M = 73728, m-tile 256)
    const int W_BLKS = (int)(WN / 1024);

    zero_stats_kernel<<<1, 64>>>();

    // tf32 RN rounding of weights (inputs are rounded in-register by embed GEMMs)
    cvt_tf32_kernel<<<W_BLKS, 256>>>(embed_w, w_embed);
    cvt_tf32_kernel<<<W_BLKS, 256>>>(v_w, w_v);
    cvt_tf32_kernel<<<W_BLKS, 256>>>(q_w, w_q);
    cvt_tf32_kernel<<<W_BLKS, 256>>>(k_w, w_k);
    cvt_tf32_kernel<<<W_BLKS, 256>>>(out_w, w_out);

    // LN of raw inputs (independent of embed path)
    ln_kernel<<<MROWS, 256>>>(attn_rgb, lns, ln_w, ln_b);
    ln_kernel<<<MROWS, 256>>>(attn_tir, lns + SLAB, ln_w, ln_b);

    // embed GEMMs: raw A, fragment rounding, fused BN stats
    tgemm_kernel<true, true><<<grid1, 256, TF_SMEM>>>(attn_rgb, w_embed, embed_b,
                                                      emb, stats + 0);
    tgemm_kernel<true, true><<<grid1, 256, TF_SMEM>>>(attn_tir, w_embed, embed_b,
                                                      emb + SLAB, stats + 24);

    // BN finalize + apply (+pos), both streams in one launch
    bn_finalize_kernel<<<1, 32>>>(bn_w, bn_b);
    bn_apply_kernel<<<2 * MROWS, 256>>>(emb, pos_emb, norm);

    // V GEMM (merged pair), Q and K GEMMs (merged pairs)
    tgemm_kernel<false, false><<<grid2, 256, TF_SMEM>>>(lns, w_v, v_b, vbuf, nullptr);
    tgemm_kernel<false, false><<<grid2, 256, TF_SMEM>>>(norm, w_q, q_b, qbuf, nullptr);
    tgemm_kernel<false, false><<<grid2, 256, TF_SMEM>>>(norm, w_k, k_b, kbuf, nullptr);

    // fused attention -> tf32-rounded outputs (overwrites ln slabs)
    attn_kernel<<<dim3(BHCOUNT, 2), 256>>>(qbuf, qbuf + SLAB, kbuf, kbuf + SLAB,
                                           vbuf, vbuf + SLAB, lns, lns + SLAB);

    // output projection (merged pair) straight into d_out
    tgemm_kernel<false, false><<<grid2, 256, TF_SMEM>>>(lns, w_out, out_b, out, nullptr);
}

// round 16
// speedup vs baseline: 1.0914x; 1.0914x over previous
#include <cuda_runtime.h>
#include <cuda_bf16.h>
#include <math.h>
#include <stdint.h>

// Shapes: B=256, hn=12, N1=12, dim=inner=1024
#define MROWS   36864
#define BHCOUNT 3072
#define DIM     1024
#define SLAB    37748736ULL          // MROWS * DIM

// fp32 slabs: 0 emb_r, 1 emb_t, 2 norm_r, 3 norm_t, 4 ln_r(->ao_r), 5 ln_t(->ao_t),
//             6 q_r, 7 q_t, 8 k_r, 9 k_t, 10 v_r, 11 v_t   (pairs adjacent)
__device__ float g_f32[12 * SLAB];
__device__ float g_w[5ULL * 1024 * 1024];   // tf32-rounded weights
__device__ float g_stats[48];   // [0:12) sum_r, [12:24) sq_r, [24:36) sum_t, [36:48) sq_t
__device__ float g_coef[48];

// ---------------------------------------------------------------------------
__global__ void zero_stats_kernel() {
    if (threadIdx.x < 48) g_stats[threadIdx.x] = 0.0f;
}

// ---------------------------------------------------------------------------
// helpers
// ---------------------------------------------------------------------------
__device__ __forceinline__ uint32_t swz128(uint32_t o) { return o ^ ((o >> 3) & 0x70); }

__device__ __forceinline__ void cp_async16(uint32_t saddr, const void* gaddr) {
    asm volatile("cp.async.cg.shared.global [%0], [%1], 16;\n" :: "r"(saddr), "l"(gaddr));
}
__device__ __forceinline__ void cp_commit() { asm volatile("cp.async.commit_group;\n"); }

__device__ __forceinline__ float to_tf32(float x) {
    float r;
    asm("cvt.rna.tf32.f32 %0, %1;" : "=f"(r) : "f"(x));
    return r;
}
__device__ __forceinline__ uint32_t round_u32(uint32_t x) {
    return __float_as_uint(to_tf32(__uint_as_float(x)));
}

__device__ __forceinline__ void ldsm4(uint32_t& r0, uint32_t& r1, uint32_t& r2,
                                      uint32_t& r3, uint32_t addr) {
    asm volatile("ldmatrix.sync.aligned.m8n8.x4.shared.b16 {%0,%1,%2,%3}, [%4];\n"
                 : "=r"(r0), "=r"(r1), "=r"(r2), "=r"(r3) : "r"(addr));
}

__device__ __forceinline__ void mma_tf32(float* d, const uint32_t* a, const uint32_t* b) {
    asm volatile(
        "mma.sync.aligned.m16n8k8.row.col.f32.tf32.tf32.f32 "
        "{%0,%1,%2,%3},{%4,%5,%6,%7},{%8,%9},{%0,%1,%2,%3};\n"
        : "+f"(d[0]), "+f"(d[1]), "+f"(d[2]), "+f"(d[3])
        : "r"(a[0]), "r"(a[1]), "r"(a[2]), "r"(a[3]), "r"(b[0]), "r"(b[1]));
}

__device__ __forceinline__ uint32_t smem_u32(const void* p) {
    uint32_t a;
    asm("{ .reg .u64 t; cvta.to.shared.u64 t, %1; cvt.u32.u64 %0, t; }" : "=r"(a) : "l"(p));
    return a;
}

// ---------------------------------------------------------------------------
// round an fp32 array to tf32 (RN). grid = n/1024, block 256, float4/thread.
// ---------------------------------------------------------------------------
__global__ void cvt_tf32_kernel(const float* __restrict__ in, float* __restrict__ out)
{
    size_t i = ((size_t)blockIdx.x * 256 + threadIdx.x) * 4;
    float4 v = *(const float4*)(in + i);
    v.x = to_tf32(v.x); v.y = to_tf32(v.y);
    v.z = to_tf32(v.z); v.w = to_tf32(v.w);
    *(float4*)(out + i) = v;
}

// ---------------------------------------------------------------------------
// tf32 GEMM (round-13 proven config): C[M,1024] = A @ W^T + bias.
// Block tile 128x128, k-tile 32 floats, 3-stage cp.async, prefetch-2,
// one __syncthreads per k-tile, 256 threads, warp tile 32x64, 2 CTAs/SM.
// DO_STATS mode is ALSO dual-stream: m-tiles [0,MH) read A0, [MH,2*MH) read A1,
// stats go to statsPtr + 0 / + 24. Otherwise A0 only.
// ---------------------------------------------------------------------------
#define TFSTAGE 32768
#define TF_SMEM (3 * TFSTAGE)
#define MH 288                        // m-tiles per stream in dual mode (MROWS/128)

template<bool ROUND_A, bool DO_STATS>
__global__ __launch_bounds__(256, 2) void tgemm_kernel(
    const float* __restrict__ A0, const float* __restrict__ A1,
    const float* __restrict__ W,
    const float* __restrict__ bias, float* __restrict__ C,
    float* __restrict__ statsPtr)
{
    extern __shared__ char smem[];
    __shared__ float s_sum[128], s_sq[128];
    const uint32_t tiles = smem_u32(smem);
    const int tid = threadIdx.x, lane = tid & 31, warp = tid >> 5;
    const int bm = blockIdx.y, bn = blockIdx.x;
    const int m_off = (warp >> 1) * 32, n_off = (warp & 1) * 64;
    const int r0 = tid >> 3;     // 0..31
    const int ch = tid & 7;      // 16B chunk within 128B row

    // A source / local row base
    const float* Abase = A0;
    int lm = bm;                 // m-tile index within its stream
    if (DO_STATS) {
        if (bm >= MH) { Abase = A1; lm = bm - MH; }
    }

    if (DO_STATS) {
        if (tid < 128) { s_sum[tid] = 0.0f; s_sq[tid] = 0.0f; }
    }

    float acc[2][8][4];
#pragma unroll
    for (int i = 0; i < 2; i++)
#pragma unroll
        for (int j = 0; j < 8; j++)
#pragma unroll
            for (int r = 0; r < 4; r++) acc[i][j][r] = 0.0f;

    auto load_tile = [&](int stage, int kt) {
        const float* Ag = Abase + (size_t)(lm * 128 + r0) * DIM + kt * 32 + ch * 4;
        const float* Wg = W + (size_t)(bn * 128 + r0) * DIM + kt * 32 + ch * 4;
        uint32_t sa = tiles + stage * TFSTAGE;
        uint32_t sb = sa + 16384;
#pragma unroll
        for (int j = 0; j < 4; j++) {
            uint32_t so = swz128((uint32_t)(r0 + 32 * j) * 128 + ch * 16);
            cp_async16(sa + so, Ag + (size_t)(32 * j) * DIM);
            cp_async16(sb + so, Wg + (size_t)(32 * j) * DIM);
        }
        cp_commit();
    };

    load_tile(0, 0); load_tile(1, 1);

#pragma unroll 1
    for (int kt = 0; kt < 32; kt++) {
        if (kt < 31) asm volatile("cp.async.wait_group 1;\n" ::: "memory");
        else         asm volatile("cp.async.wait_group 0;\n" ::: "memory");
        __syncthreads();

        if (kt + 2 < 32) load_tile((kt + 2) % 3, kt + 2);

        uint32_t sa = tiles + (kt % 3) * TFSTAGE;
        uint32_t sb = sa + 16384;
#pragma unroll
        for (int kk = 0; kk < 4; kk++) {           // 4 k8 steps per 32-float tile
            uint32_t afr[2][4], bfr[8][2];
#pragma unroll
            for (int i = 0; i < 2; i++) {
                int row = m_off + i * 16 + (lane & 15);
                uint32_t addr = sa + swz128((uint32_t)row * 128 + (2 * kk + (lane >> 4)) * 16);
                ldsm4(afr[i][0], afr[i][1], afr[i][2], afr[i][3], addr);
                if (ROUND_A) {
#pragma unroll
                    for (int r = 0; r < 4; r++) afr[i][r] = round_u32(afr[i][r]);
                }
            }
#pragma unroll
            for (int jj = 0; jj < 4; jj++) {
                int row = n_off + jj * 16 + (lane & 7) + ((lane >> 4) << 3);
                uint32_t addr = sb + swz128((uint32_t)row * 128 + (2 * kk + ((lane >> 3) & 1)) * 16);
                ldsm4(bfr[2 * jj][0], bfr[2 * jj][1], bfr[2 * jj + 1][0], bfr[2 * jj + 1][1], addr);
            }
#pragma unroll
            for (int i = 0; i < 2; i++)
#pragma unroll
                for (int j = 0; j < 8; j++) mma_tf32(acc[i][j], afr[i], bfr[j]);
        }
    }

    // epilogue (C indexed by GLOBAL m-tile bm; A was indexed by local lm)
    const int gr = lane >> 2, gc = (lane & 3) * 2;
    float rsum[4] = {0, 0, 0, 0}, rsq[4] = {0, 0, 0, 0};
#pragma unroll
    for (int i = 0; i < 2; i++) {
        size_t rowg = (size_t)(bm * 128 + m_off + i * 16 + gr);
#pragma unroll
        for (int j = 0; j < 8; j++) {
            int col = bn * 128 + n_off + j * 8 + gc;
            float b0 = __ldg(bias + col), b1 = __ldg(bias + col + 1);
            float2 o0 = make_float2(acc[i][j][0] + b0, acc[i][j][1] + b1);
            float2 o1 = make_float2(acc[i][j][2] + b0, acc[i][j][3] + b1);
            *(float2*)(C + rowg * DIM + col)       = o0;
            *(float2*)(C + (rowg + 8) * DIM + col) = o1;
            if (DO_STATS) {
                rsum[2 * i]     += o0.x + o0.y;
                rsq[2 * i]      += o0.x * o0.x + o0.y * o0.y;
                rsum[2 * i + 1] += o1.x + o1.y;
                rsq[2 * i + 1]  += o1.x * o1.x + o1.y * o1.y;
            }
        }
    }

    if (DO_STATS) {
#pragma unroll
        for (int i = 0; i < 2; i++) {
            int lr = m_off + i * 16 + gr;
            atomicAdd(&s_sum[lr],     rsum[2 * i]);
            atomicAdd(&s_sq[lr],      rsq[2 * i]);
            atomicAdd(&s_sum[lr + 8], rsum[2 * i + 1]);
            atomicAdd(&s_sq[lr + 8],  rsq[2 * i + 1]);
        }
        __syncthreads();
        if (tid < 128) {
            float* sp = statsPtr + ((bm >= MH) ? 24 : 0);
            int c = (lm * 128 + tid) % 12;
            atomicAdd(&sp[c],      s_sum[tid]);
            atomicAdd(&sp[12 + c], s_sq[tid]);
        }
    }
}

// ---------------------------------------------------------------------------
// BN finalize: stats -> per-channel affine coefficients (both streams)
// ---------------------------------------------------------------------------
__global__ void bn_finalize_kernel(const float* __restrict__ bn_w,
                                   const float* __restrict__ bn_b)
{
    int c = threadIdx.x;
    if (c >= 12) return;
    const float inv_cnt = 1.0f / 3145728.0f;
    {
        float mean = g_stats[c] * inv_cnt;
        float var  = g_stats[12 + c] * inv_cnt - mean * mean;
        float A = bn_w[c] * rsqrtf(var + 1e-5f);
        g_coef[c] = A;  g_coef[12 + c] = bn_b[c] - mean * A;
    }
    {
        float mean = g_stats[24 + c] * inv_cnt;
        float var  = g_stats[36 + c] * inv_cnt - mean * mean;
        float A = bn_w[c] * rsqrtf(var + 1e-5f);
        g_coef[24 + c] = A;  g_coef[36 + c] = bn_b[c] - mean * A;
    }
}

// ---------------------------------------------------------------------------
// BN apply + pos add, tf32-rounded fp32 output. BOTH streams in one launch.
// ---------------------------------------------------------------------------
__global__ void bn_apply_kernel(const float* __restrict__ emb,   // slab 0 (r|t)
                                const float* __restrict__ pos,
                                float* __restrict__ normout)     // slab 2 (r|t)
{
    size_t row = blockIdx.x;             // 0 .. 2*MROWS-1
    int t = threadIdx.x;
    int stream = (int)(row >= MROWS);
    size_t lrow = row - (size_t)stream * MROWS;
    int coef_off = stream * 24;
    int c = (int)(lrow % 12);
    size_t b = lrow / 144;
    float A  = g_coef[coef_off + c];
    float Bc = g_coef[coef_off + 12 + c];
    float4 v = ((const float4*)(emb + row * DIM))[t];
    float4 p = ((const float4*)(pos + (b * 12 + (size_t)c) * DIM))[t];
    float4 o;
    o.x = to_tf32(v.x * A + Bc + p.x);
    o.y = to_tf32(v.y * A + Bc + p.y);
    o.z = to_tf32(v.z * A + Bc + p.z);
    o.w = to_tf32(v.w * A + Bc + p.w);
    ((float4*)(normout + row * DIM))[t] = o;
}

// ---------------------------------------------------------------------------
// LayerNorm, warp-per-row, both streams in one launch.
// grid = 2*MROWS/8, block 256 (8 warps = 8 rows). Shuffle-only reduction.
// ---------------------------------------------------------------------------
__global__ void ln2_kernel(const float* __restrict__ src_r,
                           const float* __restrict__ src_t,
                           float* __restrict__ dst,              // slab 4 (r|t)
                           const float* __restrict__ w, const float* __restrict__ b)
{
    size_t row = (size_t)blockIdx.x * 8 + (threadIdx.x >> 5);    // 0..2*MROWS-1
    const int lane = threadIdx.x & 31;
    const float* src = (row < MROWS) ? (src_r + row * DIM)
                                     : (src_t + (row - MROWS) * DIM);
    const float4* p = (const float4*)src;

    float4 v[8];
    float s = 0.0f, q = 0.0f;
#pragma unroll
    for (int i = 0; i < 8; i++) {
        v[i] = p[lane + 32 * i];
        s += v[i].x + v[i].y + v[i].z + v[i].w;
        q += v[i].x * v[i].x + v[i].y * v[i].y + v[i].z * v[i].z + v[i].w * v[i].w;
    }
#pragma unroll
    for (int o = 16; o; o >>= 1) {
        s += __shfl_xor_sync(0xffffffffu, s, o);
        q += __shfl_xor_sync(0xffffffffu, q, o);
    }
    float mean = s * (1.0f / 1024.0f);
    float var  = q * (1.0f / 1024.0f) - mean * mean;
    float inv  = rsqrtf(var + 1e-5f);

    float4* d = (float4*)(dst + row * DIM);
#pragma unroll
    for (int i = 0; i < 8; i++) {
        float4 wv = ((const float4*)w)[lane + 32 * i];
        float4 bv = ((const float4*)b)[lane + 32 * i];
        float4 o;
        o.x = to_tf32((v[i].x - mean) * inv * wv.x + bv.x);
        o.y = to_tf32((v[i].y - mean) * inv * wv.y + bv.y);
        o.z = to_tf32((v[i].z - mean) * inv * wv.z + bv.z);
        o.w = to_tf32((v[i].w - mean) * inv * wv.w + bv.w);
        d[lane + 32 * i] = o;
    }
}

// ---------------------------------------------------------------------------
// fused attention, BOTH streams per block (shared K/V reads):
// logits(2x12x24) -> softmax -> attn @ V; tf32-rounded output.
// grid = 3072, block 256.
// ---------------------------------------------------------------------------
__global__ void attn_kernel(const float* __restrict__ q_r, const float* __restrict__ q_t,
                            const float* __restrict__ k_r, const float* __restrict__ k_t,
                            const float* __restrict__ v_r, const float* __restrict__ v_t,
                            float* __restrict__ ao_r, float* __restrict__ ao_t)
{
    const int bh = blockIdx.x;
    const size_t base = (size_t)bh * 12 * DIM;
    const float* Qs[2] = { q_r + base, q_t + base };
    float*       AOs[2] = { ao_r + base, ao_t + base };
    const float* Kr = k_r + base;
    const float* Kt = k_t + base;
    const float* Vr = v_r + base;
    const float* Vt = v_t + base;

    __shared__ float att[2][12][24];
    const int tid = threadIdx.x, lane = tid & 31, wrp = tid >> 5;

    // 576 dot products (2 streams x 12 q-rows x 24 keys), 8 warps
    for (int dot = wrp; dot < 576; dot += 8) {
        int st = dot / 288;
        int r  = dot % 288;
        int n1 = r / 24, s = r % 24;
        const float4* qp = (const float4*)(Qs[st] + (size_t)n1 * DIM);
        const float4* kp = (const float4*)((s < 12) ? (Kr + (size_t)s * DIM)
                                                    : (Kt + (size_t)(s - 12) * DIM));
        float acc = 0.0f;
        for (int d4 = lane; d4 < 256; d4 += 32) {
            float4 a = qp[d4]; float4 bb = kp[d4];
            acc += a.x * bb.x + a.y * bb.y + a.z * bb.z + a.w * bb.w;
        }
#pragma unroll
        for (int o = 16; o; o >>= 1) acc += __shfl_xor_sync(0xffffffffu, acc, o);
        if (lane == 0) att[st][n1][s] = acc;
    }
    __syncthreads();

    if (tid < 24) {
        int st = tid / 12, n1 = tid % 12;
        const float scale = 0.03125f;
        float e[24], m = -1e30f;
#pragma unroll
        for (int s = 0; s < 24; s++) { float l = att[st][n1][s] * scale; e[s] = l; m = fmaxf(m, l); }
        float sum = 0.0f;
#pragma unroll
        for (int s = 0; s < 24; s++) { float x = expf(e[s] - m); e[s] = x; sum += x; }
        float inv = 1.0f / sum;
#pragma unroll
        for (int s = 0; s < 24; s++) att[st][n1][s] = e[s] * inv;
    }
    __syncthreads();

    for (int d = tid; d < DIM; d += 256) {
        float vc[24];
#pragma unroll
        for (int s = 0; s < 12; s++) vc[s]      = Vr[(size_t)s * DIM + d];
#pragma unroll
        for (int s = 0; s < 12; s++) vc[12 + s] = Vt[(size_t)s * DIM + d];
#pragma unroll
        for (int st = 0; st < 2; st++) {
#pragma unroll
            for (int n1 = 0; n1 < 12; n1++) {
                float o = 0.0f;
#pragma unroll
                for (int s = 0; s < 24; s++) o += att[st][n1][s] * vc[s];
                AOs[st][(size_t)n1 * DIM + d] = to_tf32(o);
            }
        }
    }
}

// ---------------------------------------------------------------------------
extern "C" void kernel_launch(void* const* d_in, const int* in_sizes, int n_in,
                              void* d_out, int out_size)
{
    const float* attn_rgb = (const float*)d_in[0];
    const float* attn_tir = (const float*)d_in[1];
    const float* pos_emb  = (const float*)d_in[2];
    const float* embed_w  = (const float*)d_in[3];
    const float* embed_b  = (const float*)d_in[4];
    const float* bn_w     = (const float*)d_in[5];
    const float* bn_b     = (const float*)d_in[6];
    const float* ln_w     = (const float*)d_in[7];
    const float* ln_b     = (const float*)d_in[8];
    const float* v_w      = (const float*)d_in[9];
    const float* v_b      = (const float*)d_in[10];
    const float* q_w      = (const float*)d_in[11];
    const float* q_b      = (const float*)d_in[12];
    const float* k_w      = (const float*)d_in[13];
    const float* k_b      = (const float*)d_in[14];
    const float* out_w    = (const float*)d_in[15];
    const float* out_b    = (const float*)d_in[16];
    float* out = (float*)d_out;

    float* f32 = nullptr;   cudaGetSymbolAddress((void**)&f32, g_f32);
    float* wbuf = nullptr;  cudaGetSymbolAddress((void**)&wbuf, g_w);
    float* stats = nullptr; cudaGetSymbolAddress((void**)&stats, g_stats);

    float* emb   = f32 + 0 * SLAB;    // [0,1]: emb_r | emb_t
    float* norm  = f32 + 2 * SLAB;    // [2,3]: norm_r | norm_t
    float* lns   = f32 + 4 * SLAB;    // [4,5]: ln_r | ln_t  (reused as ao after V)
    float* qbuf  = f32 + 6 * SLAB;    // [6,7]
    float* kbuf  = f32 + 8 * SLAB;    // [8,9]
    float* vbuf  = f32 + 10 * SLAB;   // [10,11]

    const size_t WN = 1024ULL * 1024;
    float* w_embed = wbuf + 0 * WN;
    float* w_v     = wbuf + 1 * WN;
    float* w_q     = wbuf + 2 * WN;
    float* w_k     = wbuf + 3 * WN;
    float* w_out   = wbuf + 4 * WN;

    cudaFuncSetAttribute(tgemm_kernel<false, false>,
                         cudaFuncAttributeMaxDynamicSharedMemorySize, TF_SMEM);
    cudaFuncSetAttribute(tgemm_kernel<true, true>,
                         cudaFuncAttributeMaxDynamicSharedMemorySize, TF_SMEM);

    const dim3 grid2(8, 576);    // merged-pair GEMM: M = 73728 = 576 m-tiles of 128
    const int W_BLKS = (int)(WN / 1024);

    zero_stats_kernel<<<1, 64>>>();

    // tf32 RN rounding of weights (inputs are rounded in-register by embed GEMMs)
    cvt_tf32_kernel<<<W_BLKS, 256>>>(embed_w, w_embed);
    cvt_tf32_kernel<<<W_BLKS, 256>>>(v_w, w_v);
    cvt_tf32_kernel<<<W_BLKS, 256>>>(q_w, w_q);
    cvt_tf32_kernel<<<W_BLKS, 256>>>(k_w, w_k);
    cvt_tf32_kernel<<<W_BLKS, 256>>>(out_w, w_out);

    // LN of raw inputs, both streams, warp-per-row
    ln2_kernel<<<2 * MROWS / 8, 256>>>(attn_rgb, attn_tir, lns, ln_w, ln_b);

    // embed GEMM: both streams in ONE launch, raw A + in-register rounding,
    // fused BN stats (per-half)
    tgemm_kernel<true, true><<<grid2, 256, TF_SMEM>>>(attn_rgb, attn_tir, w_embed,
                                                      embed_b, emb, stats);

    // BN finalize + apply (+pos), both streams in one launch
    bn_finalize_kernel<<<1, 32>>>(bn_w, bn_b);
    bn_apply_kernel<<<2 * MROWS, 256>>>(emb, pos_emb, norm);

    // V GEMM (merged pair), Q and K GEMMs (merged pairs)
    tgemm_kernel<false, false><<<grid2, 256, TF_SMEM>>>(lns, nullptr, w_v, v_b, vbuf, nullptr);
    tgemm_kernel<false, false><<<grid2, 256, TF_SMEM>>>(norm, nullptr, w_q, q_b, qbuf, nullptr);
    tgemm_kernel<false, false><<<grid2, 256, TF_SMEM>>>(norm, nullptr, w_k, k_b, kbuf, nullptr);

    // fused attention (both streams per block) -> overwrites ln slabs
    attn_kernel<<<BHCOUNT, 256>>>(qbuf, qbuf + SLAB, kbuf, kbuf + SLAB,
                                  vbuf, vbuf + SLAB, lns, lns + SLAB);

    // output projection (merged pair) straight into d_out
    tgemm_kernel<false, false><<<grid2, 256, TF_SMEM>>>(lns, nullptr, w_out, out_b, out, nullptr);
}

// round 17
// speedup vs baseline: 1.4294x; 1.3096x over previous
#include <cuda_runtime.h>
#include <cuda_bf16.h>
#include <math.h>
#include <stdint.h>

// Shapes: B=256, hn=12, N1=12, dim=inner=1024
#define MROWS   36864
#define BHCOUNT 3072
#define DIM     1024
#define SLAB    37748736ULL          // MROWS * DIM

// fp32 slabs: 0 emb_r, 1 emb_t, 2 norm_r, 3 norm_t, 4 ln_r, 5 ln_t,
//             6 zx_r, 7 zx_t, 8 ao_r, 9 ao_t   (pairs adjacent)
__device__ float g_f32[10 * SLAB];
// weights (1024x1024 each): 0 w_embed, 1 qT, 2 kT, 3 vT, 4 Wt, 5 Wvo
__device__ float g_w[6ULL * 1024 * 1024];
__device__ float g_stats[48];   // [0:12) sum_r, [12:24) sq_r, [24:36) sum_t, [36:48) sq_t
__device__ float g_coef[48];
__device__ float g_abuf[1024];  // q_w^T k_b
__device__ float g_bbuf[1024];  // k_w^T q_b
__device__ float g_bias2[1024]; // out_w v_b + out_b
__device__ float g_cscal[1];    // q_b . k_b
__device__ float g_zero[1024];  // stays zero (never written)

// ---------------------------------------------------------------------------
__global__ void zero_stats_kernel() {
    if (threadIdx.x < 48) g_stats[threadIdx.x] = 0.0f;
}

// ---------------------------------------------------------------------------
// helpers
// ---------------------------------------------------------------------------
__device__ __forceinline__ uint32_t swz128(uint32_t o) { return o ^ ((o >> 3) & 0x70); }

__device__ __forceinline__ void cp_async16(uint32_t saddr, const void* gaddr) {
    asm volatile("cp.async.cg.shared.global [%0], [%1], 16;\n" :: "r"(saddr), "l"(gaddr));
}
__device__ __forceinline__ void cp_commit() { asm volatile("cp.async.commit_group;\n"); }

__device__ __forceinline__ float to_tf32(float x) {
    float r;
    asm("cvt.rna.tf32.f32 %0, %1;" : "=f"(r) : "f"(x));
    return r;
}
__device__ __forceinline__ uint32_t round_u32(uint32_t x) {
    return __float_as_uint(to_tf32(__uint_as_float(x)));
}

__device__ __forceinline__ void ldsm4(uint32_t& r0, uint32_t& r1, uint32_t& r2,
                                      uint32_t& r3, uint32_t addr) {
    asm volatile("ldmatrix.sync.aligned.m8n8.x4.shared.b16 {%0,%1,%2,%3}, [%4];\n"
                 : "=r"(r0), "=r"(r1), "=r"(r2), "=r"(r3) : "r"(addr));
}

__device__ __forceinline__ void mma_tf32(float* d, const uint32_t* a, const uint32_t* b) {
    asm volatile(
        "mma.sync.aligned.m16n8k8.row.col.f32.tf32.tf32.f32 "
        "{%0,%1,%2,%3},{%4,%5,%6,%7},{%8,%9},{%0,%1,%2,%3};\n"
        : "+f"(d[0]), "+f"(d[1]), "+f"(d[2]), "+f"(d[3])
        : "r"(a[0]), "r"(a[1]), "r"(a[2]), "r"(a[3]), "r"(b[0]), "r"(b[1]));
}

__device__ __forceinline__ uint32_t smem_u32(const void* p) {
    uint32_t a;
    asm("{ .reg .u64 t; cvta.to.shared.u64 t, %1; cvt.u32.u64 %0, t; }" : "=r"(a) : "l"(p));
    return a;
}

// ---------------------------------------------------------------------------
// round an fp32 array to tf32 (RN). grid = n/1024, block 256.
// ---------------------------------------------------------------------------
__global__ void cvt_tf32_kernel(const float* __restrict__ in, float* __restrict__ out)
{
    size_t i = ((size_t)blockIdx.x * 256 + threadIdx.x) * 4;
    float4 v = *(const float4*)(in + i);
    v.x = to_tf32(v.x); v.y = to_tf32(v.y);
    v.z = to_tf32(v.z); v.w = to_tf32(v.w);
    *(float4*)(out + i) = v;
}

// ---------------------------------------------------------------------------
// transpose 1024x1024 with tf32 rounding: out[x][y] = tf32(in[y][x])
// grid (32,32), block (32,8)
// ---------------------------------------------------------------------------
__global__ void transpose_round_kernel(const float* __restrict__ in,
                                       float* __restrict__ out)
{
    __shared__ float t[32][33];
    int x0 = blockIdx.x * 32, y0 = blockIdx.y * 32;
    int tx = threadIdx.x, ty = threadIdx.y;
#pragma unroll
    for (int i = ty; i < 32; i += 8)
        t[i][tx] = in[(size_t)(y0 + i) * DIM + x0 + tx];
    __syncthreads();
#pragma unroll
    for (int i = ty; i < 32; i += 8)
        out[(size_t)(x0 + i) * DIM + y0 + tx] = to_tf32(t[tx][i]);
}

// ---------------------------------------------------------------------------
// aux vectors: a = q_w^T k_b, b = k_w^T q_b, bias2 = out_w v_b + out_b,
// c = q_b . k_b.  grid = 1024, block = 256.
// ---------------------------------------------------------------------------
__global__ void aux_kernel(const float* __restrict__ q_w, const float* __restrict__ k_w,
                           const float* __restrict__ out_w,
                           const float* __restrict__ q_b, const float* __restrict__ k_b,
                           const float* __restrict__ v_b, const float* __restrict__ out_b)
{
    const int o = blockIdx.x, tid = threadIdx.x, lane = tid & 31, wrp = tid >> 5;
    __shared__ float ra[8], rb[8], rv[8], rc[8];
    float sa = 0, sb = 0, sv = 0, sc = 0;
    for (int t = tid; t < DIM; t += 256) {
        sa += q_w[(size_t)t * DIM + o] * k_b[t];
        sb += k_w[(size_t)t * DIM + o] * q_b[t];
        sv += out_w[(size_t)o * DIM + t] * v_b[t];
        if (blockIdx.x == 0) sc += q_b[t] * k_b[t];
    }
#pragma unroll
    for (int off = 16; off; off >>= 1) {
        sa += __shfl_xor_sync(0xffffffffu, sa, off);
        sb += __shfl_xor_sync(0xffffffffu, sb, off);
        sv += __shfl_xor_sync(0xffffffffu, sv, off);
        sc += __shfl_xor_sync(0xffffffffu, sc, off);
    }
    if (lane == 0) { ra[wrp] = sa; rb[wrp] = sb; rv[wrp] = sv; rc[wrp] = sc; }
    __syncthreads();
    if (tid == 0) {
        float A = 0, B = 0, V = 0, C = 0;
#pragma unroll
        for (int i = 0; i < 8; i++) { A += ra[i]; B += rb[i]; V += rv[i]; C += rc[i]; }
        g_abuf[o] = A;
        g_bbuf[o] = B;
        g_bias2[o] = V + out_b[o];
        if (blockIdx.x == 0) g_cscal[0] = C;
    }
}

// ---------------------------------------------------------------------------
// tf32 GEMM (proven 128x128 config): C[M,1024] = A @ W^T + bias.
// 3-stage cp.async, prefetch-2, one barrier/k-tile, 256 thr, 2 CTAs/SM.
// ROUND_A: round A fragments in-register. DO_STATS: dual-stream + BN stats.
// ROUND_C: tf32-round the output (for precomputed weight products).
// ---------------------------------------------------------------------------
#define TFSTAGE 32768
#define TF_SMEM (3 * TFSTAGE)
#define MH 288                        // m-tiles per stream in dual mode

template<bool ROUND_A, bool DO_STATS, bool ROUND_C>
__global__ __launch_bounds__(256, 2) void tgemm_kernel(
    const float* __restrict__ A0, const float* __restrict__ A1,
    const float* __restrict__ W,
    const float* __restrict__ bias, float* __restrict__ C,
    float* __restrict__ statsPtr)
{
    extern __shared__ char smem[];
    __shared__ float s_sum[128], s_sq[128];
    const uint32_t tiles = smem_u32(smem);
    const int tid = threadIdx.x, lane = tid & 31, warp = tid >> 5;
    const int bm = blockIdx.y, bn = blockIdx.x;
    const int m_off = (warp >> 1) * 32, n_off = (warp & 1) * 64;
    const int r0 = tid >> 3;
    const int ch = tid & 7;

    const float* Abase = A0;
    int lm = bm;
    if (DO_STATS) {
        if (bm >= MH) { Abase = A1; lm = bm - MH; }
    }

    if (DO_STATS) {
        if (tid < 128) { s_sum[tid] = 0.0f; s_sq[tid] = 0.0f; }
    }

    float acc[2][8][4];
#pragma unroll
    for (int i = 0; i < 2; i++)
#pragma unroll
        for (int j = 0; j < 8; j++)
#pragma unroll
            for (int r = 0; r < 4; r++) acc[i][j][r] = 0.0f;

    auto load_tile = [&](int stage, int kt) {
        const float* Ag = Abase + (size_t)(lm * 128 + r0) * DIM + kt * 32 + ch * 4;
        const float* Wg = W + (size_t)(bn * 128 + r0) * DIM + kt * 32 + ch * 4;
        uint32_t sa = tiles + stage * TFSTAGE;
        uint32_t sb = sa + 16384;
#pragma unroll
        for (int j = 0; j < 4; j++) {
            uint32_t so = swz128((uint32_t)(r0 + 32 * j) * 128 + ch * 16);
            cp_async16(sa + so, Ag + (size_t)(32 * j) * DIM);
            cp_async16(sb + so, Wg + (size_t)(32 * j) * DIM);
        }
        cp_commit();
    };

    load_tile(0, 0); load_tile(1, 1);

#pragma unroll 1
    for (int kt = 0; kt < 32; kt++) {
        if (kt < 31) asm volatile("cp.async.wait_group 1;\n" ::: "memory");
        else         asm volatile("cp.async.wait_group 0;\n" ::: "memory");
        __syncthreads();

        if (kt + 2 < 32) load_tile((kt + 2) % 3, kt + 2);

        uint32_t sa = tiles + (kt % 3) * TFSTAGE;
        uint32_t sb = sa + 16384;
#pragma unroll
        for (int kk = 0; kk < 4; kk++) {
            uint32_t afr[2][4], bfr[8][2];
#pragma unroll
            for (int i = 0; i < 2; i++) {
                int row = m_off + i * 16 + (lane & 15);
                uint32_t addr = sa + swz128((uint32_t)row * 128 + (2 * kk + (lane >> 4)) * 16);
                ldsm4(afr[i][0], afr[i][1], afr[i][2], afr[i][3], addr);
                if (ROUND_A) {
#pragma unroll
                    for (int r = 0; r < 4; r++) afr[i][r] = round_u32(afr[i][r]);
                }
            }
#pragma unroll
            for (int jj = 0; jj < 4; jj++) {
                int row = n_off + jj * 16 + (lane & 7) + ((lane >> 4) << 3);
                uint32_t addr = sb + swz128((uint32_t)row * 128 + (2 * kk + ((lane >> 3) & 1)) * 16);
                ldsm4(bfr[2 * jj][0], bfr[2 * jj][1], bfr[2 * jj + 1][0], bfr[2 * jj + 1][1], addr);
            }
#pragma unroll
            for (int i = 0; i < 2; i++)
#pragma unroll
                for (int j = 0; j < 8; j++) mma_tf32(acc[i][j], afr[i], bfr[j]);
        }
    }

    const int gr = lane >> 2, gc = (lane & 3) * 2;
    float rsum[4] = {0, 0, 0, 0}, rsq[4] = {0, 0, 0, 0};
#pragma unroll
    for (int i = 0; i < 2; i++) {
        size_t rowg = (size_t)(bm * 128 + m_off + i * 16 + gr);
#pragma unroll
        for (int j = 0; j < 8; j++) {
            int col = bn * 128 + n_off + j * 8 + gc;
            float b0 = __ldg(bias + col), b1 = __ldg(bias + col + 1);
            float2 o0 = make_float2(acc[i][j][0] + b0, acc[i][j][1] + b1);
            float2 o1 = make_float2(acc[i][j][2] + b0, acc[i][j][3] + b1);
            if (ROUND_C) {
                o0.x = to_tf32(o0.x); o0.y = to_tf32(o0.y);
                o1.x = to_tf32(o1.x); o1.y = to_tf32(o1.y);
            }
            *(float2*)(C + rowg * DIM + col)       = o0;
            *(float2*)(C + (rowg + 8) * DIM + col) = o1;
            if (DO_STATS) {
                rsum[2 * i]     += o0.x + o0.y;
                rsq[2 * i]      += o0.x * o0.x + o0.y * o0.y;
                rsum[2 * i + 1] += o1.x + o1.y;
                rsq[2 * i + 1]  += o1.x * o1.x + o1.y * o1.y;
            }
        }
    }

    if (DO_STATS) {
#pragma unroll
        for (int i = 0; i < 2; i++) {
            int lr = m_off + i * 16 + gr;
            atomicAdd(&s_sum[lr],     rsum[2 * i]);
            atomicAdd(&s_sq[lr],      rsq[2 * i]);
            atomicAdd(&s_sum[lr + 8], rsum[2 * i + 1]);
            atomicAdd(&s_sq[lr + 8],  rsq[2 * i + 1]);
        }
        __syncthreads();
        if (tid < 128) {
            float* sp = statsPtr + ((bm >= MH) ? 24 : 0);
            int c = (lm * 128 + tid) % 12;
            atomicAdd(&sp[c],      s_sum[tid]);
            atomicAdd(&sp[12 + c], s_sq[tid]);
        }
    }
}

// ---------------------------------------------------------------------------
// BN finalize
// ---------------------------------------------------------------------------
__global__ void bn_finalize_kernel(const float* __restrict__ bn_w,
                                   const float* __restrict__ bn_b)
{
    int c = threadIdx.x;
    if (c >= 12) return;
    const float inv_cnt = 1.0f / 3145728.0f;
    {
        float mean = g_stats[c] * inv_cnt;
        float var  = g_stats[12 + c] * inv_cnt - mean * mean;
        float A = bn_w[c] * rsqrtf(var + 1e-5f);
        g_coef[c] = A;  g_coef[12 + c] = bn_b[c] - mean * A;
    }
    {
        float mean = g_stats[24 + c] * inv_cnt;
        float var  = g_stats[36 + c] * inv_cnt - mean * mean;
        float A = bn_w[c] * rsqrtf(var + 1e-5f);
        g_coef[24 + c] = A;  g_coef[36 + c] = bn_b[c] - mean * A;
    }
}

// ---------------------------------------------------------------------------
// BN apply + pos add, tf32-rounded. Both streams in one launch.
// ---------------------------------------------------------------------------
__global__ void bn_apply_kernel(const float* __restrict__ emb,
                                const float* __restrict__ pos,
                                float* __restrict__ normout)
{
    size_t row = blockIdx.x;
    int t = threadIdx.x;
    int stream = (int)(row >= MROWS);
    size_t lrow = row - (size_t)stream * MROWS;
    int coef_off = stream * 24;
    int c = (int)(lrow % 12);
    size_t b = lrow / 144;
    float A  = g_coef[coef_off + c];
    float Bc = g_coef[coef_off + 12 + c];
    float4 v = ((const float4*)(emb + row * DIM))[t];
    float4 p = ((const float4*)(pos + (b * 12 + (size_t)c) * DIM))[t];
    float4 o;
    o.x = to_tf32(v.x * A + Bc + p.x);
    o.y = to_tf32(v.y * A + Bc + p.y);
    o.z = to_tf32(v.z * A + Bc + p.z);
    o.w = to_tf32(v.w * A + Bc + p.w);
    ((float4*)(normout + row * DIM))[t] = o;
}

// ---------------------------------------------------------------------------
// LayerNorm, warp-per-row, both streams in one launch.
// ---------------------------------------------------------------------------
__global__ void ln2_kernel(const float* __restrict__ src_r,
                           const float* __restrict__ src_t,
                           float* __restrict__ dst,
                           const float* __restrict__ w, const float* __restrict__ b)
{
    size_t row = (size_t)blockIdx.x * 8 + (threadIdx.x >> 5);
    const int lane = threadIdx.x & 31;
    const float* src = (row < MROWS) ? (src_r + row * DIM)
                                     : (src_t + (row - MROWS) * DIM);
    const float4* p = (const float4*)src;

    float4 v[8];
    float s = 0.0f, q = 0.0f;
#pragma unroll
    for (int i = 0; i < 8; i++) {
        v[i] = p[lane + 32 * i];
        s += v[i].x + v[i].y + v[i].z + v[i].w;
        q += v[i].x * v[i].x + v[i].y * v[i].y + v[i].z * v[i].z + v[i].w * v[i].w;
    }
#pragma unroll
    for (int o = 16; o; o >>= 1) {
        s += __shfl_xor_sync(0xffffffffu, s, o);
        q += __shfl_xor_sync(0xffffffffu, q, o);
    }
    float mean = s * (1.0f / 1024.0f);
    float var  = q * (1.0f / 1024.0f) - mean * mean;
    float inv  = rsqrtf(var + 1e-5f);

    float4* d = (float4*)(dst + row * DIM);
#pragma unroll
    for (int i = 0; i < 8; i++) {
        float4 wv = ((const float4*)w)[lane + 32 * i];
        float4 bv = ((const float4*)b)[lane + 32 * i];
        float4 o;
        o.x = to_tf32((v[i].x - mean) * inv * wv.x + bv.x);
        o.y = to_tf32((v[i].y - mean) * inv * wv.y + bv.y);
        o.z = to_tf32((v[i].z - mean) * inv * wv.z + bv.z);
        o.w = to_tf32((v[i].w - mean) * inv * wv.w + bv.w);
        d[lane + 32 * i] = o;
    }
}

// ---------------------------------------------------------------------------
// fused attention, both streams per block. Q-side = Zx rows, K-side = norm
// rows, V-side = ln rows. logits = Zx_i.norm_j + a.norm_i + b.norm_j + c.
// Output ao' = attnW @ ln (tf32-rounded), to be hit by the Wvo GEMM.
// grid = 3072, block 256.
// ---------------------------------------------------------------------------
__global__ void attn_kernel(const float* __restrict__ zx,    // slabs 6,7
                            const float* __restrict__ nrm,   // slabs 2,3
                            const float* __restrict__ lns,   // slabs 4,5
                            float* __restrict__ ao)          // slabs 8,9
{
    const int bh = blockIdx.x;
    const size_t base = (size_t)bh * 12 * DIM;

    __shared__ float att[2][12][24];
    __shared__ float aux_a[24], aux_b[24];
    const int tid = threadIdx.x, lane = tid & 31, wrp = tid >> 5;

    // 576 logit dots + 24 a-dots + 24 b-dots
    for (int dot = wrp; dot < 624; dot += 8) {
        const float4 *xp, *yp;
        float acc = 0.0f;
        if (dot < 576) {
            int st = dot / 288, r = dot % 288;
            int n1 = r / 24, s = r % 24;
            xp = (const float4*)(zx + (size_t)st * SLAB + base + (size_t)n1 * DIM);
            yp = (const float4*)(nrm + (size_t)(s / 12) * SLAB + base + (size_t)(s % 12) * DIM);
            for (int d4 = lane; d4 < 256; d4 += 32) {
                float4 a = xp[d4]; float4 bb = yp[d4];
                acc += a.x * bb.x + a.y * bb.y + a.z * bb.z + a.w * bb.w;
            }
#pragma unroll
            for (int o = 16; o; o >>= 1) acc += __shfl_xor_sync(0xffffffffu, acc, o);
            if (lane == 0) att[st][n1][s] = acc;
        } else {
            int s = (dot - 576) % 24;
            bool isA = (dot < 600);
            xp = (const float4*)(nrm + (size_t)(s / 12) * SLAB + base + (size_t)(s % 12) * DIM);
            yp = (const float4*)(isA ? g_abuf : g_bbuf);
            for (int d4 = lane; d4 < 256; d4 += 32) {
                float4 a = xp[d4]; float4 bb = yp[d4];
                acc += a.x * bb.x + a.y * bb.y + a.z * bb.z + a.w * bb.w;
            }
#pragma unroll
            for (int o = 16; o; o >>= 1) acc += __shfl_xor_sync(0xffffffffu, acc, o);
            if (lane == 0) { if (isA) aux_a[s] = acc; else aux_b[s] = acc; }
        }
    }
    __syncthreads();

    if (tid < 24) {
        int st = tid / 12, n1 = tid % 12;
        const float scale = 0.03125f;
        const float cval = g_cscal[0];
        float xa = aux_a[st * 12 + n1];
        float e[24], m = -1e30f;
#pragma unroll
        for (int s = 0; s < 24; s++) {
            float l = (att[st][n1][s] + xa + aux_b[s] + cval) * scale;
            e[s] = l;
            m = fmaxf(m, l);
        }
        float sum = 0.0f;
#pragma unroll
        for (int s = 0; s < 24; s++) { float x = expf(e[s] - m); e[s] = x; sum += x; }
        float inv = 1.0f / sum;
#pragma unroll
        for (int s = 0; s < 24; s++) att[st][n1][s] = e[s] * inv;
    }
    __syncthreads();

    const float* Vr = lns + base;
    const float* Vt = lns + SLAB + base;
    for (int d = tid; d < DIM; d += 256) {
        float vc[24];
#pragma unroll
        for (int s = 0; s < 12; s++) vc[s]      = Vr[(size_t)s * DIM + d];
#pragma unroll
        for (int s = 0; s < 12; s++) vc[12 + s] = Vt[(size_t)s * DIM + d];
#pragma unroll
        for (int st = 0; st < 2; st++) {
#pragma unroll
            for (int n1 = 0; n1 < 12; n1++) {
                float o = 0.0f;
#pragma unroll
                for (int s = 0; s < 24; s++) o += att[st][n1][s] * vc[s];
                ao[(size_t)st * SLAB + base + (size_t)n1 * DIM + d] = to_tf32(o);
            }
        }
    }
}

// ---------------------------------------------------------------------------
extern "C" void kernel_launch(void* const* d_in, const int* in_sizes, int n_in,
                              void* d_out, int out_size)
{
    const float* attn_rgb = (const float*)d_in[0];
    const float* attn_tir = (const float*)d_in[1];
    const float* pos_emb  = (const float*)d_in[2];
    const float* embed_w  = (const float*)d_in[3];
    const float* embed_b  = (const float*)d_in[4];
    const float* bn_w     = (const float*)d_in[5];
    const float* bn_b     = (const float*)d_in[6];
    const float* ln_w     = (const float*)d_in[7];
    const float* ln_b     = (const float*)d_in[8];
    const float* v_w      = (const float*)d_in[9];
    const float* v_b      = (const float*)d_in[10];
    const float* q_w      = (const float*)d_in[11];
    const float* q_b      = (const float*)d_in[12];
    const float* k_w      = (const float*)d_in[13];
    const float* k_b      = (const float*)d_in[14];
    const float* out_w    = (const float*)d_in[15];
    const float* out_b    = (const float*)d_in[16];
    float* out = (float*)d_out;

    float* f32 = nullptr;   cudaGetSymbolAddress((void**)&f32, g_f32);
    float* wbuf = nullptr;  cudaGetSymbolAddress((void**)&wbuf, g_w);
    float* stats = nullptr; cudaGetSymbolAddress((void**)&stats, g_stats);
    float* zerob = nullptr; cudaGetSymbolAddress((void**)&zerob, g_zero);
    float* bias2 = nullptr; cudaGetSymbolAddress((void**)&bias2, g_bias2);

    float* emb   = f32 + 0 * SLAB;    // [0,1]
    float* norm  = f32 + 2 * SLAB;    // [2,3]
    float* lns   = f32 + 4 * SLAB;    // [4,5]
    float* zxbuf = f32 + 6 * SLAB;    // [6,7]
    float* aobuf = f32 + 8 * SLAB;    // [8,9]

    const size_t WN = 1024ULL * 1024;
    float* w_embed = wbuf + 0 * WN;
    float* qT      = wbuf + 1 * WN;
    float* kT      = wbuf + 2 * WN;
    float* vT      = wbuf + 3 * WN;
    float* Wt      = wbuf + 4 * WN;   // k_w^T q_w (tf32-rounded)
    float* Wvo     = wbuf + 5 * WN;   // out_w v_w (tf32-rounded)

    cudaFuncSetAttribute(tgemm_kernel<true, true, false>,
                         cudaFuncAttributeMaxDynamicSharedMemorySize, TF_SMEM);
    cudaFuncSetAttribute(tgemm_kernel<false, false, false>,
                         cudaFuncAttributeMaxDynamicSharedMemorySize, TF_SMEM);
    cudaFuncSetAttribute(tgemm_kernel<false, false, true>,
                         cudaFuncAttributeMaxDynamicSharedMemorySize, TF_SMEM);
    cudaFuncSetAttribute(tgemm_kernel<true, false, true>,
                         cudaFuncAttributeMaxDynamicSharedMemorySize, TF_SMEM);

    const dim3 grid2(8, 576);    // merged-pair big GEMM: M = 73728
    const dim3 gridW(8, 8);      // weight-product GEMM: M = 1024
    const dim3 tgrid(32, 32), tblk(32, 8);

    zero_stats_kernel<<<1, 64>>>();

    // weight prep
    cvt_tf32_kernel<<<1024, 256>>>(embed_w, w_embed);
    transpose_round_kernel<<<tgrid, tblk>>>(q_w, qT);
    transpose_round_kernel<<<tgrid, tblk>>>(k_w, kT);
    transpose_round_kernel<<<tgrid, tblk>>>(v_w, vT);
    aux_kernel<<<1024, 256>>>(q_w, k_w, out_w, q_b, k_b, v_b, out_b);

    // weight products (tiny GEMMs, tf32-rounded outputs)
    // Wt = kT @ qT^T = k_w^T q_w;  Wvo = out_w @ vT^T = out_w v_w
    tgemm_kernel<false, false, true><<<gridW, 256, TF_SMEM>>>(kT, nullptr, qT,
                                                              zerob, Wt, nullptr);
    tgemm_kernel<true, false, true><<<gridW, 256, TF_SMEM>>>(out_w, nullptr, vT,
                                                             zerob, Wvo, nullptr);

    // LN of raw inputs, both streams
    ln2_kernel<<<2 * MROWS / 8, 256>>>(attn_rgb, attn_tir, lns, ln_w, ln_b);

    // embed GEMM (dual-stream, in-register A rounding, fused BN stats)
    tgemm_kernel<true, true, false><<<grid2, 256, TF_SMEM>>>(attn_rgb, attn_tir,
                                                             w_embed, embed_b, emb, stats);

    // BN finalize + apply (+pos)
    bn_finalize_kernel<<<1, 32>>>(bn_w, bn_b);
    bn_apply_kernel<<<2 * MROWS, 256>>>(emb, pos_emb, norm);

    // Zx = norm @ Wt^T  (replaces Q and K GEMMs)
    tgemm_kernel<false, false, false><<<grid2, 256, TF_SMEM>>>(norm, nullptr, Wt,
                                                               zerob, zxbuf, nullptr);

    // fused attention on (Zx, norm, ln) -> ao'
    attn_kernel<<<BHCOUNT, 256>>>(zxbuf, norm, lns, aobuf);

    // out = ao' @ Wvo^T + bias2  (replaces V GEMM + out-proj GEMM)
    tgemm_kernel<false, false, false><<<grid2, 256, TF_SMEM>>>(aobuf, nullptr, Wvo,
                                                               bias2, out, nullptr);
}